// round 2
// baseline (speedup 1.0000x reference)
#include <cuda_runtime.h>
#include <math.h>

#define HH 128
#define WW 160
#define CC 32
#define DD 32
#define BB 2
#define VV 5
#define HWSZ (HH*WW)       // 20480
#define NPIX (BB*HWSZ)     // 40960

// out layout (flattened tuple in reference-return order):
#define OFF_DEPTH 0
#define OFF_CONF  40960
#define OFF_PROB  81920
#define OFF_COST  1392640
#define OFF_VW    2703360

__device__ float g_rot[4][BB][9];
__device__ float g_trans[4][BB][3];
// g_mlp layout: [0:16) A0, [16:32) C0, [32:160) W1f(j*16+o), [160:168) C1, [168:176) W2, [176] B2
__device__ float g_mlp[177];
__device__ float g_sim[BB*DD*HWSZ];

// ---------------------------------------------------------------------------
// Prep: build proj matrices (K@E top, E bottom row), invert ref (double,
// Gauss-Jordan w/ pivot), P = src @ inv(ref); fold BN into MLP affines.
// ---------------------------------------------------------------------------
__global__ void prep_kernel(const float* __restrict__ pm,
    const float* __restrict__ w0, const float* __restrict__ g0,
    const float* __restrict__ b0, const float* __restrict__ m0, const float* __restrict__ v0,
    const float* __restrict__ w1, const float* __restrict__ g1,
    const float* __restrict__ b1, const float* __restrict__ m1, const float* __restrict__ v1,
    const float* __restrict__ w2, const float* __restrict__ b2)
{
    int t = threadIdx.x;
    if (t < 8) {
        int b = t >> 2;
        int v = (t & 3) + 1;
        double refM[4][4], srcM[4][4];
        for (int which = 0; which < 2; ++which) {
            int view = which ? v : 0;
            const float* E = pm + ((b*VV + view)*2 + 0)*16;
            const float* K = pm + ((b*VV + view)*2 + 1)*16;
            double (*M)[4] = which ? srcM : refM;
            for (int r = 0; r < 3; ++r)
                for (int c = 0; c < 4; ++c) {
                    double s = 0.0;
                    for (int k = 0; k < 3; ++k) s += (double)K[r*4+k] * (double)E[k*4+c];
                    M[r][c] = s;
                }
            for (int c = 0; c < 4; ++c) M[3][c] = (double)E[12 + c];
        }
        // Gauss-Jordan inverse of refM (double, partial pivot)
        double a[4][8];
        for (int r = 0; r < 4; ++r)
            for (int c = 0; c < 4; ++c) { a[r][c] = refM[r][c]; a[r][c+4] = (r==c) ? 1.0 : 0.0; }
        for (int col = 0; col < 4; ++col) {
            int piv = col; double best = fabs(a[col][col]);
            for (int r = col+1; r < 4; ++r) { double mg = fabs(a[r][col]); if (mg > best) { best = mg; piv = r; } }
            if (piv != col)
                for (int c = 0; c < 8; ++c) { double tmp = a[col][c]; a[col][c] = a[piv][c]; a[piv][c] = tmp; }
            double dinv = 1.0 / a[col][col];
            for (int c = 0; c < 8; ++c) a[col][c] *= dinv;
            for (int r = 0; r < 4; ++r) if (r != col) {
                double f = a[r][col];
                for (int c = 0; c < 8; ++c) a[r][c] -= f * a[col][c];
            }
        }
        // P = srcM @ inv(refM), keep top 3 rows
        for (int r = 0; r < 3; ++r)
            for (int c = 0; c < 4; ++c) {
                double s = 0.0;
                for (int k = 0; k < 4; ++k) s += srcM[r][k] * a[k][c+4];
                if (c < 3) g_rot[v-1][b][r*3+c] = (float)s;
                else       g_trans[v-1][b][r]   = (float)s;
            }
    } else if (t == 8) {
        for (int o = 0; o < 16; ++o) {
            float ai = g0[o] / sqrtf(v0[o] + 1e-5f);
            g_mlp[o]      = w0[o] * ai;
            g_mlp[16 + o] = b0[o] - m0[o] * ai;
        }
        for (int j = 0; j < 8; ++j) {
            float ai = g1[j] / sqrtf(v1[j] + 1e-5f);
            for (int o = 0; o < 16; ++o) g_mlp[32 + j*16 + o] = w1[j*16 + o] * ai;
            g_mlp[160 + j] = b1[j] - m1[j] * ai;
            g_mlp[168 + j] = w2[j];
        }
        g_mlp[176] = b2[0];
    }
}

// ---------------------------------------------------------------------------
// Fused: homography warp + bilinear gather + channel dot (sim), per-element
// MLP + sigmoid + max over D (view weight), weighted accumulation over views.
// Thread = (b,h,w); D-vector of sims staged in shared (saves 32 regs).
// ---------------------------------------------------------------------------
__global__ void __launch_bounds__(128) sim_kernel(const float* __restrict__ feat,
                                                  const float* __restrict__ depthv,
                                                  float* __restrict__ out)
{
    __shared__ float sp[177];
    __shared__ float ssim[DD*128];
    for (int i = threadIdx.x; i < 177; i += 128) sp[i] = g_mlp[i];
    __syncthreads();

    int g  = blockIdx.x * 128 + threadIdx.x;   // NPIX = 320*128 exactly
    int b  = g / HWSZ;
    int hw = g - b*HWSZ;
    int h  = hw / WW, w = hw - h*WW;
    float xf = (float)w, yf = (float)h;

    const float* ref = feat + (b*CC)*HWSZ + hw;
    float refv[CC];
    #pragma unroll
    for (int c = 0; c < CC; ++c) refv[c] = __ldg(ref + c*HWSZ);

    float acc[DD];
    #pragma unroll
    for (int d = 0; d < DD; ++d) acc[d] = 0.f;
    float wsum = 1e-5f;

    const float* depcol = depthv + (b*DD)*HWSZ + hw;

    for (int v = 1; v < VV; ++v) {
        const float* R = g_rot[v-1][b];
        const float* T = g_trans[v-1][b];
        float rx = R[0]*xf + R[1]*yf + R[2];
        float ry = R[3]*xf + R[4]*yf + R[5];
        float rz = R[6]*xf + R[7]*yf + R[8];
        float tx = T[0], ty = T[1], tz = T[2];
        const float* src = feat + ((v*BB + b)*CC)*HWSZ;
        float vmax = -1e30f;

        for (int d = 0; d < DD; ++d) {
            float dep = __ldg(depcol + d*HWSZ);
            float px = fmaf(rx, dep, tx);
            float py = fmaf(ry, dep, ty);
            float pz = fmaf(rz, dep, tz);
            float iz = 1.0f / pz;
            float xs = px * iz, ys = py * iz;      // grid un-normalization cancels
            float x0f = floorf(xs), y0f = floorf(ys);
            float wx = xs - x0f, wy = ys - y0f;
            int ix = (int)x0f, iy = (int)y0f;
            float w00 = (1.f-wx)*(1.f-wy), w01 = wx*(1.f-wy);
            float w10 = (1.f-wx)*wy,       w11 = wx*wy;
            bool vx0 = (ix   >= 0) && (ix   < WW);
            bool vx1 = (ix+1 >= 0) && (ix+1 < WW);
            bool vy0 = (iy   >= 0) && (iy   < HH);
            bool vy1 = (iy+1 >= 0) && (iy+1 < HH);
            if (!(vx0 && vy0)) w00 = 0.f;
            if (!(vx1 && vy0)) w01 = 0.f;
            if (!(vx0 && vy1)) w10 = 0.f;
            if (!(vx1 && vy1)) w11 = 0.f;
            int x0c = min(max(ix,   0), WW-1), x1c = min(max(ix+1, 0), WW-1);
            int y0c = min(max(iy,   0), HH-1), y1c = min(max(iy+1, 0), HH-1);
            int o00 = y0c*WW + x0c, o01 = y0c*WW + x1c;
            int o10 = y1c*WW + x0c, o11 = y1c*WW + x1c;

            float s = 0.f;
            #pragma unroll
            for (int c = 0; c < CC; ++c) {
                const float* p = src + c*HWSZ;
                float tap = fmaf(w00, __ldg(p+o00),
                            fmaf(w01, __ldg(p+o01),
                            fmaf(w10, __ldg(p+o10), w11 * __ldg(p+o11))));
                s = fmaf(tap, refv[c], s);
            }
            float sim = s * (1.f/32.f);
            ssim[d*128 + threadIdx.x] = sim;

            // folded MLP: 1 -> 16 -> 8 -> 1, sigmoid
            float tt[16];
            #pragma unroll
            for (int o = 0; o < 16; ++o) tt[o] = fmaxf(fmaf(sim, sp[o], sp[16+o]), 0.f);
            float o2 = sp[176];
            #pragma unroll
            for (int j = 0; j < 8; ++j) {
                float u = sp[160+j];
                #pragma unroll
                for (int o = 0; o < 16; ++o) u = fmaf(sp[32 + j*16 + o], tt[o], u);
                o2 = fmaf(sp[168+j], fmaxf(u, 0.f), o2);
            }
            float sg = 1.f / (1.f + __expf(-o2));
            vmax = fmaxf(vmax, sg);
        }

        out[OFF_VW + (b*4 + (v-1))*HWSZ + hw] = vmax;
        wsum += vmax;
        #pragma unroll
        for (int d = 0; d < DD; ++d)
            acc[d] = fmaf(ssim[d*128 + threadIdx.x], vmax, acc[d]);
    }

    float invw = 1.f / wsum;
    float* so = g_sim + (b*DD)*HWSZ + hw;
    #pragma unroll
    for (int d = 0; d < DD; ++d) so[d*HWSZ] = acc[d] * invw;
}

// ---------------------------------------------------------------------------
// 3x3x3 conv (SAME, zero pad) + softmax over D + argmax -> depth/conf,
// writes prob_volume and cost_reg. Thread = (b,h,w); D fully unrolled so
// cost[] stays in registers; each depth slice's 9 taps loaded once.
// ---------------------------------------------------------------------------
__global__ void __launch_bounds__(128) post_kernel(const float* __restrict__ depthv,
                                                   const float* __restrict__ regw,
                                                   const float* __restrict__ regb,
                                                   float* __restrict__ out)
{
    __shared__ float rw[27];
    __shared__ float rb;
    if (threadIdx.x < 27) rw[threadIdx.x] = regw[threadIdx.x];
    if (threadIdx.x == 27) rb = regb[0];
    __syncthreads();

    int g  = blockIdx.x * 128 + threadIdx.x;
    int b  = g / HWSZ;
    int hw = g - b*HWSZ;
    int h  = hw / WW, w = hw - h*WW;
    const float* simb = g_sim + (b*DD)*HWSZ;

    float cost[DD];
    #pragma unroll
    for (int d = 0; d < DD; ++d) cost[d] = rb;

    #pragma unroll
    for (int dd = 0; dd < DD; ++dd) {
        float s[9];
        #pragma unroll
        for (int kh = 0; kh < 3; ++kh)
            #pragma unroll
            for (int kw = 0; kw < 3; ++kw) {
                int h2 = h + kh - 1, w2 = w + kw - 1;
                s[kh*3+kw] = (h2 >= 0 && h2 < HH && w2 >= 0 && w2 < WW)
                             ? __ldg(simb + dd*HWSZ + h2*WW + w2) : 0.f;
            }
        #pragma unroll
        for (int kd = 0; kd < 3; ++kd) {
            int d = dd + 1 - kd;           // compile-time after unroll
            if (d >= 0 && d < DD) {
                float p = 0.f;
                #pragma unroll
                for (int i = 0; i < 9; ++i) p = fmaf(rw[kd*9+i], s[i], p);
                cost[d] += p;
            }
        }
    }

    float m = cost[0];
    #pragma unroll
    for (int d = 1; d < DD; ++d) m = fmaxf(m, cost[d]);
    float e[DD]; float sum = 0.f;
    #pragma unroll
    for (int d = 0; d < DD; ++d) { e[d] = __expf(cost[d] - m); sum += e[d]; }
    float isum = 1.f / sum;

    int idx = 0; float best = cost[0];
    #pragma unroll
    for (int d = 1; d < DD; ++d) if (cost[d] > best) { best = cost[d]; idx = d; }

    out[OFF_DEPTH + g] = __ldg(depthv + (b*DD + idx)*HWSZ + hw);
    out[OFF_CONF  + g] = isum;   // max prob = exp(0)/sum
    #pragma unroll
    for (int d = 0; d < DD; ++d) {
        out[OFF_PROB + (b*DD + d)*HWSZ + hw] = e[d] * isum;
        out[OFF_COST + (b*DD + d)*HWSZ + hw] = cost[d];
    }
}

extern "C" void kernel_launch(void* const* d_in, const int* in_sizes, int n_in,
                              void* d_out, int out_size)
{
    const float* feat   = (const float*)d_in[0];
    const float* pm     = (const float*)d_in[1];
    const float* depthv = (const float*)d_in[2];
    // num_depth is a python int scalar; some harness layouts include it as
    // d_in[3] (size-1 tensor), some drop it. Derive the param base index.
    int base = (n_in >= 18) ? 4 : 3;
    const float* w0 = (const float*)d_in[base + 0];
    const float* g0 = (const float*)d_in[base + 1];
    const float* b0 = (const float*)d_in[base + 2];
    const float* m0 = (const float*)d_in[base + 3];
    const float* v0 = (const float*)d_in[base + 4];
    const float* w1 = (const float*)d_in[base + 5];
    const float* g1 = (const float*)d_in[base + 6];
    const float* b1 = (const float*)d_in[base + 7];
    const float* m1 = (const float*)d_in[base + 8];
    const float* v1 = (const float*)d_in[base + 9];
    const float* w2 = (const float*)d_in[base + 10];
    const float* b2 = (const float*)d_in[base + 11];
    const float* regw = (const float*)d_in[base + 12];
    const float* regb = (const float*)d_in[base + 13];
    float* out = (float*)d_out;

    prep_kernel<<<1, 32>>>(pm, w0, g0, b0, m0, v0, w1, g1, b1, m1, v1, w2, b2);
    sim_kernel<<<NPIX/128, 128>>>(feat, depthv, out);
    post_kernel<<<NPIX/128, 128>>>(depthv, regw, regb, out);
}

// round 4
// speedup vs baseline: 1.0090x; 1.0090x over previous
#include <cuda_runtime.h>
#include <math.h>

#define HH 128
#define WW 160
#define CC 32
#define DD 32
#define BB 2
#define VV 5
#define HWSZ (HH*WW)       // 20480
#define NPIX (BB*HWSZ)     // 40960
#define NPLANE (VV*BB*(CC/4))   // 80 float4-planes

// out layout (flattened tuple in reference-return order):
#define OFF_DEPTH 0
#define OFF_CONF  40960
#define OFF_PROB  81920
#define OFF_COST  1392640
#define OFF_VW    2703360

__device__ float g_rot[4][BB][9];
__device__ float g_trans[4][BB][3];
// g_mlp layout: [0:16) A0, [16:32) C0, [32:160) W1f(j*16+o), [160:168) C1, [168:176) W2, [176] B2
__device__ float g_mlp[177];
__device__ float g_sim[BB*DD*HWSZ];
// channel-quad transposed features: plane = vb*8 + c4, element = pixel, float4 = 4 channels
__device__ float4 g_featT[NPLANE*HWSZ];

// ---------------------------------------------------------------------------
// Fused transpose + prep.
// Blocks [0, NTBLK): repack features (V,B,C,H,W) -> (vb, c4, HW) float4.
// Block NTBLK: analytic proj setup (affine 4x4s -> 3x3 cofactor inverse) and
// BN folding for the pixelwise MLP.
// ---------------------------------------------------------------------------
#define NTBLK (NPLANE*HWSZ/256)   // 6400

__global__ void __launch_bounds__(256) prep_kernel(const float* __restrict__ feat,
    const float* __restrict__ pm,
    const float* __restrict__ w0, const float* __restrict__ g0,
    const float* __restrict__ b0, const float* __restrict__ m0, const float* __restrict__ v0,
    const float* __restrict__ w1, const float* __restrict__ g1,
    const float* __restrict__ b1, const float* __restrict__ m1, const float* __restrict__ v1,
    const float* __restrict__ w2, const float* __restrict__ b2)
{
    if (blockIdx.x < NTBLK) {
        int idx   = blockIdx.x * 256 + threadIdx.x;   // plane-pixel id
        int plane = idx / HWSZ;
        int p     = idx - plane*HWSZ;
        int vb = plane >> 3, c4 = plane & 7;
        const float* src = feat + ((size_t)(vb*CC + c4*4))*HWSZ + p;
        float4 v;
        v.x = __ldg(src);
        v.y = __ldg(src +   HWSZ);
        v.z = __ldg(src + 2*HWSZ);
        v.w = __ldg(src + 3*HWSZ);
        g_featT[idx] = v;
        return;
    }

    int t = threadIdx.x;
    if (t < 8) {
        int b = t >> 2;
        int v = (t & 3) + 1;
        // Build affine tops: A = K3x3 @ E3x3, tvec = K3x3 @ E[:,3]
        double Ar[9], tr[3], As[9], ts[3];
        for (int which = 0; which < 2; ++which) {
            int view = which ? v : 0;
            const float* E = pm + ((b*VV + view)*2 + 0)*16;
            const float* K = pm + ((b*VV + view)*2 + 1)*16;
            double* A = which ? As : Ar;
            double* tv = which ? ts : tr;
            for (int r = 0; r < 3; ++r) {
                for (int c = 0; c < 3; ++c) {
                    double s = 0.0;
                    for (int k = 0; k < 3; ++k) s += (double)K[r*4+k]*(double)E[k*4+c];
                    A[r*3+c] = s;
                }
                double s = 0.0;
                for (int k = 0; k < 3; ++k) s += (double)K[r*4+k]*(double)E[k*4+3];
                tv[r] = s;
            }
        }
        // Ai = inv(Ar) via cofactors
        double c00 = Ar[4]*Ar[8]-Ar[5]*Ar[7];
        double c01 = Ar[5]*Ar[6]-Ar[3]*Ar[8];
        double c02 = Ar[3]*Ar[7]-Ar[4]*Ar[6];
        double det = Ar[0]*c00 + Ar[1]*c01 + Ar[2]*c02;
        double id  = 1.0/det;
        double Ai[9];
        Ai[0] = c00*id;
        Ai[1] = (Ar[2]*Ar[7]-Ar[1]*Ar[8])*id;
        Ai[2] = (Ar[1]*Ar[5]-Ar[2]*Ar[4])*id;
        Ai[3] = c01*id;
        Ai[4] = (Ar[0]*Ar[8]-Ar[2]*Ar[6])*id;
        Ai[5] = (Ar[2]*Ar[3]-Ar[0]*Ar[5])*id;
        Ai[6] = c02*id;
        Ai[7] = (Ar[1]*Ar[6]-Ar[0]*Ar[7])*id;
        Ai[8] = (Ar[0]*Ar[4]-Ar[1]*Ar[3])*id;
        // rot = As @ Ai ; trans = ts - rot @ tr
        double rot[9];
        for (int r = 0; r < 3; ++r)
            for (int c = 0; c < 3; ++c) {
                double s = 0.0;
                for (int k = 0; k < 3; ++k) s += As[r*3+k]*Ai[k*3+c];
                rot[r*3+c] = s;
                g_rot[v-1][b][r*3+c] = (float)s;
            }
        for (int r = 0; r < 3; ++r) {
            double s = ts[r];
            for (int k = 0; k < 3; ++k) s -= rot[r*3+k]*tr[k];
            g_trans[v-1][b][r] = (float)s;
        }
    } else if (t == 8) {
        for (int o = 0; o < 16; ++o) {
            float ai = g0[o] / sqrtf(v0[o] + 1e-5f);
            g_mlp[o]      = w0[o] * ai;
            g_mlp[16 + o] = b0[o] - m0[o] * ai;
        }
        for (int j = 0; j < 8; ++j) {
            float ai = g1[j] / sqrtf(v1[j] + 1e-5f);
            for (int o = 0; o < 16; ++o) g_mlp[32 + j*16 + o] = w1[j*16 + o] * ai;
            g_mlp[160 + j] = b1[j] - m1[j] * ai;
            g_mlp[168 + j] = w2[j];
        }
        g_mlp[176] = b2[0];
    }
}

// ---------------------------------------------------------------------------
// Fused: homography warp + bilinear gather (channel-quad float4 taps) +
// channel dot (sim), per-element MLP + max-then-sigmoid (view weight),
// weighted accumulation over views. Thread = (b,h,w).
// ---------------------------------------------------------------------------
__global__ void __launch_bounds__(128) sim_kernel(const float* __restrict__ depthv,
                                                  float* __restrict__ out)
{
    __shared__ float sp[177];
    __shared__ float ssim[DD*128];
    for (int i = threadIdx.x; i < 177; i += 128) sp[i] = g_mlp[i];
    __syncthreads();

    int g  = blockIdx.x * 128 + threadIdx.x;   // NPIX = 320*128 exactly
    int b  = g / HWSZ;
    int hw = g - b*HWSZ;
    int h  = hw / WW, w = hw - h*WW;
    float xf = (float)w, yf = (float)h;

    // ref features (view 0 -> vb = b), channel quads
    float4 refv[8];
    {
        const float4* rp = g_featT + (size_t)(b*8)*HWSZ + hw;
        #pragma unroll
        for (int c4 = 0; c4 < 8; ++c4) refv[c4] = __ldg(rp + c4*HWSZ);
    }

    float acc[DD];
    #pragma unroll
    for (int d = 0; d < DD; ++d) acc[d] = 0.f;
    float wsum = 1e-5f;

    const float* depcol = depthv + (b*DD)*HWSZ + hw;

    for (int v = 1; v < VV; ++v) {
        const float* R = g_rot[v-1][b];
        const float* T = g_trans[v-1][b];
        float rx = R[0]*xf + R[1]*yf + R[2];
        float ry = R[3]*xf + R[4]*yf + R[5];
        float rz = R[6]*xf + R[7]*yf + R[8];
        float tx = T[0], ty = T[1], tz = T[2];
        const float4* srcp = g_featT + (size_t)((v*BB + b)*8)*HWSZ;
        float vmaxo = -1e30f;

        for (int d = 0; d < DD; ++d) {
            float dep = __ldg(depcol + d*HWSZ);
            float px = fmaf(rx, dep, tx);
            float py = fmaf(ry, dep, ty);
            float pz = fmaf(rz, dep, tz);
            float iz = 1.0f / pz;
            float xs = px * iz, ys = py * iz;      // grid un-normalization cancels
            float x0f = floorf(xs), y0f = floorf(ys);
            float wx = xs - x0f, wy = ys - y0f;
            int ix = (int)x0f, iy = (int)y0f;
            float w00 = (1.f-wx)*(1.f-wy), w01 = wx*(1.f-wy);
            float w10 = (1.f-wx)*wy,       w11 = wx*wy;
            bool vx0 = (ix   >= 0) && (ix   < WW);
            bool vx1 = (ix+1 >= 0) && (ix+1 < WW);
            bool vy0 = (iy   >= 0) && (iy   < HH);
            bool vy1 = (iy+1 >= 0) && (iy+1 < HH);
            if (!(vx0 && vy0)) w00 = 0.f;
            if (!(vx1 && vy0)) w01 = 0.f;
            if (!(vx0 && vy1)) w10 = 0.f;
            if (!(vx1 && vy1)) w11 = 0.f;
            int x0c = min(max(ix,   0), WW-1), x1c = min(max(ix+1, 0), WW-1);
            int y0c = min(max(iy,   0), HH-1), y1c = min(max(iy+1, 0), HH-1);
            int o00 = y0c*WW + x0c, o01 = y0c*WW + x1c;
            int o10 = y1c*WW + x0c, o11 = y1c*WW + x1c;

            float s = 0.f;
            #pragma unroll
            for (int c4 = 0; c4 < 8; ++c4) {
                const float4* pl = srcp + c4*HWSZ;
                float4 a  = __ldg(pl + o00);
                float4 bq = __ldg(pl + o01);
                float4 cq = __ldg(pl + o10);
                float4 dq = __ldg(pl + o11);
                float4 r  = refv[c4];
                float t0;
                t0 = fmaf(w00,a.x, fmaf(w01,bq.x, fmaf(w10,cq.x, w11*dq.x))); s = fmaf(t0, r.x, s);
                t0 = fmaf(w00,a.y, fmaf(w01,bq.y, fmaf(w10,cq.y, w11*dq.y))); s = fmaf(t0, r.y, s);
                t0 = fmaf(w00,a.z, fmaf(w01,bq.z, fmaf(w10,cq.z, w11*dq.z))); s = fmaf(t0, r.z, s);
                t0 = fmaf(w00,a.w, fmaf(w01,bq.w, fmaf(w10,cq.w, w11*dq.w))); s = fmaf(t0, r.w, s);
            }
            float sim = s * (1.f/32.f);
            ssim[d*128 + threadIdx.x] = sim;

            // folded MLP: 1 -> 16 -> 8 -> 1 (sigmoid deferred past the max)
            float tt[16];
            #pragma unroll
            for (int o = 0; o < 16; ++o) tt[o] = fmaxf(fmaf(sim, sp[o], sp[16+o]), 0.f);
            float o2 = sp[176];
            #pragma unroll
            for (int j = 0; j < 8; ++j) {
                float u = sp[160+j];
                #pragma unroll
                for (int o = 0; o < 16; ++o) u = fmaf(sp[32 + j*16 + o], tt[o], u);
                o2 = fmaf(sp[168+j], fmaxf(u, 0.f), o2);
            }
            vmaxo = fmaxf(vmaxo, o2);
        }

        // sigmoid is monotonic: max(sigmoid(x)) == sigmoid(max(x))
        float vmax = 1.f / (1.f + __expf(-vmaxo));
        out[OFF_VW + (b*4 + (v-1))*HWSZ + hw] = vmax;
        wsum += vmax;
        #pragma unroll
        for (int d = 0; d < DD; ++d)
            acc[d] = fmaf(ssim[d*128 + threadIdx.x], vmax, acc[d]);
    }

    float invw = 1.f / wsum;
    float* so = g_sim + (b*DD)*HWSZ + hw;
    #pragma unroll
    for (int d = 0; d < DD; ++d) so[d*HWSZ] = acc[d] * invw;
}

// ---------------------------------------------------------------------------
// 3x3x3 conv (SAME, zero pad) + softmax over D + argmax -> depth/conf,
// writes prob_volume and cost_reg. Thread = (b,h,w); D fully unrolled so
// cost[] stays in registers; each depth slice's 9 taps loaded once.
// ---------------------------------------------------------------------------
__global__ void __launch_bounds__(128) post_kernel(const float* __restrict__ depthv,
                                                   const float* __restrict__ regw,
                                                   const float* __restrict__ regb,
                                                   float* __restrict__ out)
{
    __shared__ float rw[27];
    __shared__ float rb;
    if (threadIdx.x < 27) rw[threadIdx.x] = regw[threadIdx.x];
    if (threadIdx.x == 27) rb = regb[0];
    __syncthreads();

    int g  = blockIdx.x * 128 + threadIdx.x;
    int b  = g / HWSZ;
    int hw = g - b*HWSZ;
    int h  = hw / WW, w = hw - h*WW;
    const float* simb = g_sim + (b*DD)*HWSZ;

    float cost[DD];
    #pragma unroll
    for (int d = 0; d < DD; ++d) cost[d] = rb;

    #pragma unroll
    for (int dd = 0; dd < DD; ++dd) {
        float s[9];
        #pragma unroll
        for (int kh = 0; kh < 3; ++kh)
            #pragma unroll
            for (int kw = 0; kw < 3; ++kw) {
                int h2 = h + kh - 1, w2 = w + kw - 1;
                s[kh*3+kw] = (h2 >= 0 && h2 < HH && w2 >= 0 && w2 < WW)
                             ? __ldg(simb + dd*HWSZ + h2*WW + w2) : 0.f;
            }
        #pragma unroll
        for (int kd = 0; kd < 3; ++kd) {
            int d = dd + 1 - kd;           // compile-time after unroll
            if (d >= 0 && d < DD) {
                float p = 0.f;
                #pragma unroll
                for (int i = 0; i < 9; ++i) p = fmaf(rw[kd*9+i], s[i], p);
                cost[d] += p;
            }
        }
    }

    float m = cost[0];
    #pragma unroll
    for (int d = 1; d < DD; ++d) m = fmaxf(m, cost[d]);
    float e[DD]; float sum = 0.f;
    #pragma unroll
    for (int d = 0; d < DD; ++d) { e[d] = __expf(cost[d] - m); sum += e[d]; }
    float isum = 1.f / sum;

    int idx = 0; float best = cost[0];
    #pragma unroll
    for (int d = 1; d < DD; ++d) if (cost[d] > best) { best = cost[d]; idx = d; }

    out[OFF_DEPTH + g] = __ldg(depthv + (b*DD + idx)*HWSZ + hw);
    out[OFF_CONF  + g] = isum;   // max prob = exp(0)/sum
    #pragma unroll
    for (int d = 0; d < DD; ++d) {
        out[OFF_PROB + (b*DD + d)*HWSZ + hw] = e[d] * isum;
        out[OFF_COST + (b*DD + d)*HWSZ + hw] = cost[d];
    }
}

extern "C" void kernel_launch(void* const* d_in, const int* in_sizes, int n_in,
                              void* d_out, int out_size)
{
    const float* feat   = (const float*)d_in[0];
    const float* pm     = (const float*)d_in[1];
    const float* depthv = (const float*)d_in[2];
    // num_depth is a python int scalar; some harness layouts include it as
    // d_in[3] (size-1 tensor), some drop it. Derive the param base index.
    int base = (n_in >= 18) ? 4 : 3;
    const float* w0 = (const float*)d_in[base + 0];
    const float* g0 = (const float*)d_in[base + 1];
    const float* b0 = (const float*)d_in[base + 2];
    const float* m0 = (const float*)d_in[base + 3];
    const float* v0 = (const float*)d_in[base + 4];
    const float* w1 = (const float*)d_in[base + 5];
    const float* g1 = (const float*)d_in[base + 6];
    const float* b1 = (const float*)d_in[base + 7];
    const float* m1 = (const float*)d_in[base + 8];
    const float* v1 = (const float*)d_in[base + 9];
    const float* w2 = (const float*)d_in[base + 10];
    const float* b2 = (const float*)d_in[base + 11];
    const float* regw = (const float*)d_in[base + 12];
    const float* regb = (const float*)d_in[base + 13];
    float* out = (float*)d_out;

    prep_kernel<<<NTBLK + 1, 256>>>(feat, pm, w0, g0, b0, m0, v0,
                                    w1, g1, b1, m1, v1, w2, b2);
    sim_kernel<<<NPIX/128, 128>>>(depthv, out);
    post_kernel<<<NPIX/128, 128>>>(depthv, regw, regb, out);
}